// round 3
// baseline (speedup 1.0000x reference)
#include <cuda_runtime.h>
#include <cuda_bf16.h>

#define BATCH 8192
#define DIM 10
#define ROWP 12   // padded key-row stride (floats) -> 48B, LDS.128-friendly

__device__ float g_pooled[BATCH * DIM];

typedef unsigned long long u64;

__device__ __forceinline__ u64 pack2(float lo, float hi) {
    u64 r; asm("mov.b64 %0, {%1, %2};" : "=l"(r) : "f"(lo), "f"(hi)); return r;
}
__device__ __forceinline__ float2 unpack2(u64 v) {
    float2 f; asm("mov.b64 {%0, %1}, %2;" : "=f"(f.x), "=f"(f.y) : "l"(v)); return f;
}
__device__ __forceinline__ u64 fma2(u64 a, u64 b, u64 c) {
    u64 d; asm("fma.rn.f32x2 %0, %1, %2, %3;" : "=l"(d) : "l"(a), "l"(b), "l"(c)); return d;
}
__device__ __forceinline__ u64 mul2(u64 a, u64 b) {
    u64 d; asm("mul.rn.f32x2 %0, %1, %2;" : "=l"(d) : "l"(a), "l"(b)); return d;
}
__device__ __forceinline__ u64 add2(u64 a, u64 b) {
    u64 d; asm("add.rn.f32x2 %0, %1, %2;" : "=l"(d) : "l"(a), "l"(b)); return d;
}

// ---------------------------------------------------------------------------
// Kernel 1: pooled[b,:] = (sum_n w_n * x[b,n,:]) @ W
// w_n = 0.125 * ([1,1,2] + A[0,n] + A[1,n])
// x staged through SMEM for coalesced global loads.
// ---------------------------------------------------------------------------
#define PK_NT 256
__global__ __launch_bounds__(PK_NT)
void pooled_kernel(const float* __restrict__ x,
                   const float* __restrict__ A,
                   const float* __restrict__ W) {
    __shared__ float sx[PK_NT * 3 * DIM];   // 30 KB
    __shared__ float sW[DIM * DIM];
    __shared__ float sw[3];
    int tid = threadIdx.x;
    if (tid < DIM * DIM) sW[tid] = W[tid];
    if (tid < 3) {
        const float offsum[3] = {1.f, 1.f, 2.f};
        sw[tid] = 0.125f * (offsum[tid] + A[tid] + A[3 + tid]);
    }
    int base = blockIdx.x * PK_NT * 3 * DIM;
    for (int i = tid; i < PK_NT * 3 * DIM; i += PK_NT)
        sx[i] = x[base + i];
    __syncthreads();

    const float* xb = &sx[tid * 3 * DIM];
    float w0 = sw[0], w1 = sw[1], w2 = sw[2];
    float y[DIM];
    #pragma unroll
    for (int f = 0; f < DIM; f++)
        y[f] = fmaf(w2, xb[2 * DIM + f], fmaf(w1, xb[DIM + f], w0 * xb[f]));
    int b = blockIdx.x * PK_NT + tid;
    #pragma unroll
    for (int o = 0; o < DIM; o++) {
        float acc = 0.f;
        #pragma unroll
        for (int f = 0; f < DIM; f++)
            acc = fmaf(y[f], sW[f * DIM + o], acc);
        g_pooled[b * DIM + o] = acc;
    }
}

// ---------------------------------------------------------------------------
// Kernel 2: out = softmax(P P^T) P, flash-style, packed f32x2 math.
// 128 thr/CTA = 16 groups x 8 key-parts; each group owns 2 queries.
// BQ = 32 queries/CTA, grid = 256.
// ---------------------------------------------------------------------------
#define TILE 512
#define NT 128
#define PARTS 8
#define QPT 2
#define BQ 32     // (NT/PARTS)*QPT

__global__ __launch_bounds__(NT)
void attn_kernel(float* __restrict__ out) {
    __shared__ float sk[TILE * ROWP];   // 24 KB
    __shared__ float sq[BQ * DIM];      // 1.25 KB

    int tid = threadIdx.x;
    int q0  = blockIdx.x * BQ;

    for (int i = tid; i < BQ * DIM; i += NT)
        sq[i] = g_pooled[q0 * DIM + i];
    __syncthreads();

    int grp = tid >> 3;       // 0..15
    int p   = tid & 7;        // 0..7
    int myq = grp * QPT;      // local first query

    u64 q[QPT][5];
    #pragma unroll
    for (int u = 0; u < QPT; u++)
        #pragma unroll
        for (int h = 0; h < 5; h++)
            q[u][h] = pack2(sq[(myq + u) * DIM + 2 * h],
                            sq[(myq + u) * DIM + 2 * h + 1]);

    u64 acc[QPT][5];
    float esum[QPT];
    #pragma unroll
    for (int u = 0; u < QPT; u++) {
        esum[u] = 0.f;
        #pragma unroll
        for (int h = 0; h < 5; h++) acc[u][h] = pack2(0.f, 0.f);
    }

    for (int t = 0; t < BATCH; t += TILE) {
        __syncthreads();   // previous tile fully consumed
        for (int r = tid; r < TILE; r += NT) {
            const float* src = &g_pooled[(t + r) * DIM];
            float* dst = &sk[r * ROWP];
            #pragma unroll
            for (int f = 0; f < DIM; f += 2)
                *(float2*)(dst + f) = *(const float2*)(src + f);
        }
        __syncthreads();

        #pragma unroll 2
        for (int j = p; j < TILE; j += PARTS) {
            const float4* kr = (const float4*)&sk[j * ROWP];
            float4 k0 = kr[0], k1 = kr[1], k2 = kr[2];
            u64 kp[5];
            kp[0] = pack2(k0.x, k0.y);
            kp[1] = pack2(k0.z, k0.w);
            kp[2] = pack2(k1.x, k1.y);
            kp[3] = pack2(k1.z, k1.w);
            kp[4] = pack2(k2.x, k2.y);
            #pragma unroll
            for (int u = 0; u < QPT; u++) {
                u64 s01 = mul2(q[u][0], kp[0]);
                s01 = fma2(q[u][1], kp[1], s01);
                s01 = fma2(q[u][2], kp[2], s01);
                s01 = fma2(q[u][3], kp[3], s01);
                s01 = fma2(q[u][4], kp[4], s01);
                float2 s2 = unpack2(s01);
                float e = __expf(s2.x + s2.y);
                esum[u] += e;
                u64 ee = pack2(e, e);
                #pragma unroll
                for (int h = 0; h < 5; h++)
                    acc[u][h] = fma2(ee, kp[h], acc[u][h]);
            }
        }
    }

    // reduce across the 8 key-part lanes of each group (consecutive lanes)
    #pragma unroll
    for (int off = 4; off >= 1; off >>= 1) {
        #pragma unroll
        for (int u = 0; u < QPT; u++) {
            esum[u] += __shfl_down_sync(0xffffffffu, esum[u], off);
            #pragma unroll
            for (int h = 0; h < 5; h++) {
                u64 other = __shfl_down_sync(0xffffffffu, acc[u][h], off);
                acc[u][h] = add2(acc[u][h], other);
            }
        }
    }

    if (p == 0) {
        #pragma unroll
        for (int u = 0; u < QPT; u++) {
            float inv = 1.0f / esum[u];
            float* orow = &out[(q0 + myq + u) * DIM];
            #pragma unroll
            for (int h = 0; h < 5; h++) {
                float2 v = unpack2(acc[u][h]);
                float2 o; o.x = v.x * inv; o.y = v.y * inv;
                *(float2*)(orow + 2 * h) = o;
            }
        }
    }
}

// ---------------------------------------------------------------------------
extern "C" void kernel_launch(void* const* d_in, const int* in_sizes, int n_in,
                              void* d_out, int out_size) {
    const float* x = (const float*)d_in[0];   // [8192, 3, 10]
    const float* A = (const float*)d_in[1];   // [3, 3]
    const float* W = (const float*)d_in[2];   // [10, 10]
    float* out = (float*)d_out;               // [8192, 10]

    pooled_kernel<<<BATCH / PK_NT, PK_NT>>>(x, A, W);
    attn_kernel<<<BATCH / BQ, NT>>>(out);
}

// round 4
// speedup vs baseline: 2.1221x; 2.1221x over previous
#include <cuda_runtime.h>
#include <cuda_bf16.h>

#define BATCH 8192
#define DIM 10
#define ROWP 12   // padded key-row stride (floats): 48B, 3x LDS.128 per key

__device__ float g_pooled[BATCH * DIM];

typedef unsigned long long u64;

__device__ __forceinline__ u64 pack2(float lo, float hi) {
    u64 r; asm("mov.b64 %0, {%1, %2};" : "=l"(r) : "f"(lo), "f"(hi)); return r;
}
__device__ __forceinline__ float2 unpack2(u64 v) {
    float2 f; asm("mov.b64 {%0, %1}, %2;" : "=f"(f.x), "=f"(f.y) : "l"(v)); return f;
}
__device__ __forceinline__ u64 fma2(u64 a, u64 b, u64 c) {
    u64 d; asm("fma.rn.f32x2 %0, %1, %2, %3;" : "=l"(d) : "l"(a), "l"(b), "l"(c)); return d;
}
__device__ __forceinline__ u64 mul2(u64 a, u64 b) {
    u64 d; asm("mul.rn.f32x2 %0, %1, %2;" : "=l"(d) : "l"(a), "l"(b)); return d;
}
__device__ __forceinline__ u64 add2(u64 a, u64 b) {
    u64 d; asm("add.rn.f32x2 %0, %1, %2;" : "=l"(d) : "l"(a), "l"(b)); return d;
}

// ---------------------------------------------------------------------------
// Kernel 1: pooled[b,:] = (sum_n w_n * x[b,n,:]) @ W
// ---------------------------------------------------------------------------
#define PK_NT 256
__global__ __launch_bounds__(PK_NT)
void pooled_kernel(const float* __restrict__ x,
                   const float* __restrict__ A,
                   const float* __restrict__ W) {
    __shared__ float sx[PK_NT * 3 * DIM];
    __shared__ float sW[DIM * DIM];
    __shared__ float sw[3];
    int tid = threadIdx.x;
    if (tid < DIM * DIM) sW[tid] = W[tid];
    if (tid < 3) {
        const float offsum[3] = {1.f, 1.f, 2.f};
        sw[tid] = 0.125f * (offsum[tid] + A[tid] + A[3 + tid]);
    }
    int base = blockIdx.x * PK_NT * 3 * DIM;
    for (int i = tid; i < PK_NT * 3 * DIM; i += PK_NT)
        sx[i] = x[base + i];
    __syncthreads();

    const float* xb = &sx[tid * 3 * DIM];
    float w0 = sw[0], w1 = sw[1], w2 = sw[2];
    float y[DIM];
    #pragma unroll
    for (int f = 0; f < DIM; f++)
        y[f] = fmaf(w2, xb[2 * DIM + f], fmaf(w1, xb[DIM + f], w0 * xb[f]));
    int b = blockIdx.x * PK_NT + tid;
    #pragma unroll
    for (int o = 0; o < DIM; o++) {
        float acc = 0.f;
        #pragma unroll
        for (int f = 0; f < DIM; f++)
            acc = fmaf(y[f], sW[f * DIM + o], acc);
        g_pooled[b * DIM + o] = acc;
    }
}

// ---------------------------------------------------------------------------
// Kernel 2: out = softmax(P P^T) P, flash-style, packed f32x2 math.
// NT=256: 16 groups x 16 key-parts; each group owns QPT=2 queries.
// BQ=32 queries/CTA -> grid=256 (65536 threads: full latency hiding).
// ---------------------------------------------------------------------------
#define TILE 1024
#define NT 256
#define PARTS 16
#define QPT 2
#define BQ 32     // (NT/PARTS)*QPT

__global__ __launch_bounds__(NT)
void attn_kernel(float* __restrict__ out) {
    __shared__ float sk[TILE * ROWP];   // 48 KB
    __shared__ float sq[BQ * DIM];

    int tid = threadIdx.x;
    int q0  = blockIdx.x * BQ;

    for (int i = tid; i < BQ * DIM; i += NT)
        sq[i] = g_pooled[q0 * DIM + i];
    __syncthreads();

    int grp = tid >> 4;       // 0..15
    int p   = tid & 15;       // 0..15 key-part
    int myq = grp * QPT;

    u64 q[QPT][5];
    #pragma unroll
    for (int u = 0; u < QPT; u++)
        #pragma unroll
        for (int h = 0; h < 5; h++)
            q[u][h] = pack2(sq[(myq + u) * DIM + 2 * h],
                            sq[(myq + u) * DIM + 2 * h + 1]);

    u64 acc[QPT][5];
    float esum[QPT];
    #pragma unroll
    for (int u = 0; u < QPT; u++) {
        esum[u] = 0.f;
        #pragma unroll
        for (int h = 0; h < 5; h++) acc[u][h] = pack2(0.f, 0.f);
    }

    for (int t = 0; t < BATCH; t += TILE) {
        __syncthreads();
        for (int r = tid; r < TILE; r += NT) {
            const float* src = &g_pooled[(t + r) * DIM];
            float* dst = &sk[r * ROWP];
            #pragma unroll
            for (int f = 0; f < DIM; f += 2)
                *(float2*)(dst + f) = *(const float2*)(src + f);
        }
        __syncthreads();

        #pragma unroll 4
        for (int j = p; j < TILE; j += PARTS) {
            const float4* kr = (const float4*)&sk[j * ROWP];
            float4 k0 = kr[0], k1 = kr[1], k2 = kr[2];
            u64 kp[5];
            kp[0] = pack2(k0.x, k0.y);
            kp[1] = pack2(k0.z, k0.w);
            kp[2] = pack2(k1.x, k1.y);
            kp[3] = pack2(k1.z, k1.w);
            kp[4] = pack2(k2.x, k2.y);
            #pragma unroll
            for (int u = 0; u < QPT; u++) {
                u64 s01 = mul2(q[u][0], kp[0]);
                s01 = fma2(q[u][1], kp[1], s01);
                s01 = fma2(q[u][2], kp[2], s01);
                s01 = fma2(q[u][3], kp[3], s01);
                s01 = fma2(q[u][4], kp[4], s01);
                float2 s2 = unpack2(s01);
                float e = __expf(s2.x + s2.y);
                esum[u] += e;
                u64 ee = pack2(e, e);
                #pragma unroll
                for (int h = 0; h < 5; h++)
                    acc[u][h] = fma2(ee, kp[h], acc[u][h]);
            }
        }
    }

    // reduce across the 16 key-part lanes of each group (width=16 segments)
    #pragma unroll
    for (int off = 8; off >= 1; off >>= 1) {
        #pragma unroll
        for (int u = 0; u < QPT; u++) {
            esum[u] += __shfl_down_sync(0xffffffffu, esum[u], off, 16);
            #pragma unroll
            for (int h = 0; h < 5; h++) {
                u64 other = __shfl_down_sync(0xffffffffu, acc[u][h], off, 16);
                acc[u][h] = add2(acc[u][h], other);
            }
        }
    }

    if (p == 0) {
        #pragma unroll
        for (int u = 0; u < QPT; u++) {
            float inv = 1.0f / esum[u];
            float* orow = &out[(q0 + myq + u) * DIM];
            #pragma unroll
            for (int h = 0; h < 5; h++) {
                float2 v = unpack2(acc[u][h]);
                float2 o; o.x = v.x * inv; o.y = v.y * inv;
                *(float2*)(orow + 2 * h) = o;
            }
        }
    }
}

// ---------------------------------------------------------------------------
extern "C" void kernel_launch(void* const* d_in, const int* in_sizes, int n_in,
                              void* d_out, int out_size) {
    const float* x = (const float*)d_in[0];   // [8192, 3, 10]
    const float* A = (const float*)d_in[1];   // [3, 3]
    const float* W = (const float*)d_in[2];   // [10, 10]
    float* out = (float*)d_out;               // [8192, 10]

    pooled_kernel<<<BATCH / PK_NT, PK_NT>>>(x, A, W);
    attn_kernel<<<BATCH / BQ, NT>>>(out);
}

// round 6
// speedup vs baseline: 2.1419x; 1.0093x over previous
#include <cuda_runtime.h>
#include <cuda_bf16.h>
#include <cstdint>

#define BATCH 8192
#define DIM 10
#define LOG2E 1.4426950408889634f

__device__ float g_pooled[BATCH * DIM];

typedef unsigned long long u64;
typedef unsigned int u32;

__device__ __forceinline__ u64 pack2(float lo, float hi) {
    u64 r; asm("mov.b64 %0, {%1, %2};" : "=l"(r) : "f"(lo), "f"(hi)); return r;
}
__device__ __forceinline__ float2 unpack2(u64 v) {
    float2 f; asm("mov.b64 {%0, %1}, %2;" : "=f"(f.x), "=f"(f.y) : "l"(v)); return f;
}
__device__ __forceinline__ u64 fma2(u64 a, u64 b, u64 c) {
    u64 d; asm("fma.rn.f32x2 %0, %1, %2, %3;" : "=l"(d) : "l"(a), "l"(b), "l"(c)); return d;
}
__device__ __forceinline__ u64 mul2(u64 a, u64 b) {
    u64 d; asm("mul.rn.f32x2 %0, %1, %2;" : "=l"(d) : "l"(a), "l"(b)); return d;
}
__device__ __forceinline__ u64 add2(u64 a, u64 b) {
    u64 d; asm("add.rn.f32x2 %0, %1, %2;" : "=l"(d) : "l"(a), "l"(b)); return d;
}
__device__ __forceinline__ float ex2f(float x) {
    float y; asm("ex2.approx.f32 %0, %1;" : "=f"(y) : "f"(x)); return y;
}
__device__ __forceinline__ u32 smem_u32(const void* p) {
    u32 a;
    asm("{ .reg .u64 t; cvta.to.shared.u64 t, %1; cvt.u32.u64 %0, t; }"
        : "=r"(a) : "l"(p));
    return a;
}
__device__ __forceinline__ u64 lds64(u32 addr) {
    u64 v; asm volatile("ld.shared.b64 %0, [%1];" : "=l"(v) : "r"(addr)); return v;
}

// ---------------------------------------------------------------------------
// Kernel 1: pooled[b,:] = (sum_n w_n * x[b,n,:]) @ W
// ---------------------------------------------------------------------------
#define PK_NT 128
__global__ __launch_bounds__(PK_NT)
void pooled_kernel(const float* __restrict__ x,
                   const float* __restrict__ A,
                   const float* __restrict__ W) {
    __shared__ float sx[PK_NT * 3 * DIM];
    __shared__ float sW[DIM * DIM];
    __shared__ float sw[3];
    int tid = threadIdx.x;
    if (tid < DIM * DIM) sW[tid] = W[tid];
    if (tid < 3) {
        const float offsum[3] = {1.f, 1.f, 2.f};
        sw[tid] = 0.125f * (offsum[tid] + A[tid] + A[3 + tid]);
    }
    int base = blockIdx.x * PK_NT * 3 * DIM;
    for (int i = tid; i < PK_NT * 3 * DIM; i += PK_NT)
        sx[i] = x[base + i];
    __syncthreads();

    const float* xb = &sx[tid * 3 * DIM];
    float w0 = sw[0], w1 = sw[1], w2 = sw[2];
    float y[DIM];
    #pragma unroll
    for (int f = 0; f < DIM; f++)
        y[f] = fmaf(w2, xb[2 * DIM + f], fmaf(w1, xb[DIM + f], w0 * xb[f]));
    int b = blockIdx.x * PK_NT + tid;
    #pragma unroll
    for (int o = 0; o < DIM; o++) {
        float acc = 0.f;
        #pragma unroll
        for (int f = 0; f < DIM; f++)
            acc = fmaf(y[f], sW[f * DIM + o], acc);
        g_pooled[b * DIM + o] = acc;
    }
}

// ---------------------------------------------------------------------------
// Kernel 2: out = softmax(P P^T) P, flash-style.
// NT=128, PARTS=16, QPT=2, KPT=2, BQ=16, grid=512.
// SMEM keys in 5 feature-planes of f32x2 (conflict-free LDS.64),
// double-buffered via cp.async (1 barrier/tile, fills overlap compute).
// ---------------------------------------------------------------------------
#define TILE 512
#define NTILES (BATCH / TILE)
#define NT 128
#define PARTS 16
#define QPT 2
#define BQ 16

__global__ __launch_bounds__(NT)
void attn_kernel(float* __restrict__ out) {
    // 2 buffers x 5 planes x TILE x 8B = 40960 B
    __shared__ __align__(16) float sk[2][5 * TILE * 2];

    int tid = threadIdx.x;
    int grp = tid >> 4;         // 0..7
    int p   = tid & 15;         // key-part
    int myq = blockIdx.x * BQ + grp * QPT;

    u32 sbase = smem_u32(&sk[0][0]);
    const u32 BUFB = 5 * TILE * 8;   // bytes per buffer

    // queries (pre-scaled by log2e)
    u64 q[QPT][5];
    #pragma unroll
    for (int u = 0; u < QPT; u++)
        #pragma unroll
        for (int h = 0; h < 5; h++) {
            float2 v = *(const float2*)&g_pooled[(myq + u) * DIM + 2 * h];
            q[u][h] = pack2(v.x * LOG2E, v.y * LOG2E);
        }

    u64 acc[QPT][5];
    float esum[QPT];
    #pragma unroll
    for (int u = 0; u < QPT; u++) {
        esum[u] = 0.f;
        #pragma unroll
        for (int h = 0; h < 5; h++) acc[u][h] = pack2(0.f, 0.f);
    }

    // tile fill: row r -> plane h at (h*TILE + r)*8 within buffer
    auto fill_tile = [&](int t, int buf) {
        const float* src = g_pooled + t * TILE * DIM;
        u32 dbase = sbase + buf * BUFB;
        #pragma unroll
        for (int r = tid; r < TILE; r += NT) {
            const float* s = src + r * DIM;
            u32 d = dbase + r * 8u;
            #pragma unroll
            for (int c = 0; c < 5; c++)
                asm volatile("cp.async.ca.shared.global [%0], [%1], 8;"
                             :: "r"(d + (u32)(c * TILE * 8)), "l"(s + 2 * c));
        }
        asm volatile("cp.async.commit_group;");
    };

    fill_tile(0, 0);

    for (int t = 0; t < NTILES; t++) {
        asm volatile("cp.async.wait_group 0;");
        __syncthreads();
        if (t + 1 < NTILES) fill_tile(t + 1, (t + 1) & 1);

        u32 kbase = sbase + (t & 1) * BUFB;
        #pragma unroll 2
        for (int j = p; j < TILE; j += 2 * PARTS) {
            u32 oa = kbase + j * 8u;
            u32 ob = oa + PARTS * 8u;
            u64 a0 = lds64(oa);
            u64 a1 = lds64(oa + 1 * TILE * 8);
            u64 a2 = lds64(oa + 2 * TILE * 8);
            u64 a3 = lds64(oa + 3 * TILE * 8);
            u64 a4 = lds64(oa + 4 * TILE * 8);
            u64 b0 = lds64(ob);
            u64 b1 = lds64(ob + 1 * TILE * 8);
            u64 b2 = lds64(ob + 2 * TILE * 8);
            u64 b3 = lds64(ob + 3 * TILE * 8);
            u64 b4 = lds64(ob + 4 * TILE * 8);
            #pragma unroll
            for (int u = 0; u < QPT; u++) {
                u64 sA = mul2(q[u][0], a0);
                u64 sB = mul2(q[u][0], b0);
                sA = fma2(q[u][1], a1, sA);
                sB = fma2(q[u][1], b1, sB);
                sA = fma2(q[u][2], a2, sA);
                sB = fma2(q[u][2], b2, sB);
                sA = fma2(q[u][3], a3, sA);
                sB = fma2(q[u][3], b3, sB);
                sA = fma2(q[u][4], a4, sA);
                sB = fma2(q[u][4], b4, sB);
                float2 fA = unpack2(sA);
                float2 fB = unpack2(sB);
                float eA = ex2f(fA.x + fA.y);
                float eB = ex2f(fB.x + fB.y);
                esum[u] += eA + eB;
                u64 ea = pack2(eA, eA);
                u64 eb = pack2(eB, eB);
                acc[u][0] = fma2(ea, a0, acc[u][0]);
                acc[u][1] = fma2(ea, a1, acc[u][1]);
                acc[u][2] = fma2(ea, a2, acc[u][2]);
                acc[u][3] = fma2(ea, a3, acc[u][3]);
                acc[u][4] = fma2(ea, a4, acc[u][4]);
                acc[u][0] = fma2(eb, b0, acc[u][0]);
                acc[u][1] = fma2(eb, b1, acc[u][1]);
                acc[u][2] = fma2(eb, b2, acc[u][2]);
                acc[u][3] = fma2(eb, b3, acc[u][3]);
                acc[u][4] = fma2(eb, b4, acc[u][4]);
            }
        }
    }

    // reduce across the 16 key-part lanes of each group
    #pragma unroll
    for (int off = 8; off >= 1; off >>= 1) {
        #pragma unroll
        for (int u = 0; u < QPT; u++) {
            esum[u] += __shfl_down_sync(0xffffffffu, esum[u], off, 16);
            #pragma unroll
            for (int h = 0; h < 5; h++) {
                u64 other = __shfl_down_sync(0xffffffffu, acc[u][h], off, 16);
                acc[u][h] = add2(acc[u][h], other);
            }
        }
    }

    if (p == 0) {
        #pragma unroll
        for (int u = 0; u < QPT; u++) {
            float inv = 1.0f / esum[u];
            float* orow = &out[(myq + u) * DIM];
            #pragma unroll
            for (int h = 0; h < 5; h++) {
                float2 v = unpack2(acc[u][h]);
                float2 o; o.x = v.x * inv; o.y = v.y * inv;
                *(float2*)(orow + 2 * h) = o;
            }
        }
    }
}

// ---------------------------------------------------------------------------
extern "C" void kernel_launch(void* const* d_in, const int* in_sizes, int n_in,
                              void* d_out, int out_size) {
    const float* x = (const float*)d_in[0];   // [8192, 3, 10]
    const float* A = (const float*)d_in[1];   // [3, 3]
    const float* W = (const float*)d_in[2];   // [10, 10]
    float* out = (float*)d_out;               // [8192, 10]

    pooled_kernel<<<BATCH / PK_NT, PK_NT>>>(x, A, W);
    attn_kernel<<<BATCH / BQ, NT>>>(out);
}

// round 7
// speedup vs baseline: 2.3663x; 1.1048x over previous
#include <cuda_runtime.h>
#include <cuda_bf16.h>
#include <cstdint>

#define BATCH 8192
#define DIM 10
#define LOG2E 1.4426950408889634f

__device__ float g_pooled[BATCH * DIM];

typedef unsigned long long u64;
typedef unsigned int u32;

__device__ __forceinline__ u64 pack2(float lo, float hi) {
    u64 r; asm("mov.b64 %0, {%1, %2};" : "=l"(r) : "f"(lo), "f"(hi)); return r;
}
__device__ __forceinline__ float2 unpack2(u64 v) {
    float2 f; asm("mov.b64 {%0, %1}, %2;" : "=f"(f.x), "=f"(f.y) : "l"(v)); return f;
}
__device__ __forceinline__ u64 fma2(u64 a, u64 b, u64 c) {
    u64 d; asm("fma.rn.f32x2 %0, %1, %2, %3;" : "=l"(d) : "l"(a), "l"(b), "l"(c)); return d;
}
__device__ __forceinline__ u64 mul2(u64 a, u64 b) {
    u64 d; asm("mul.rn.f32x2 %0, %1, %2;" : "=l"(d) : "l"(a), "l"(b)); return d;
}
__device__ __forceinline__ u64 add2(u64 a, u64 b) {
    u64 d; asm("add.rn.f32x2 %0, %1, %2;" : "=l"(d) : "l"(a), "l"(b)); return d;
}
__device__ __forceinline__ float ex2f(float x) {
    float y; asm("ex2.approx.f32 %0, %1;" : "=f"(y) : "f"(x)); return y;
}
__device__ __forceinline__ u32 smem_u32(const void* p) {
    u32 a;
    asm("{ .reg .u64 t; cvta.to.shared.u64 t, %1; cvt.u32.u64 %0, t; }"
        : "=r"(a) : "l"(p));
    return a;
}
__device__ __forceinline__ u64 lds64(u32 addr) {
    u64 v; asm volatile("ld.shared.b64 %0, [%1];" : "=l"(v) : "r"(addr)); return v;
}

// ---------------------------------------------------------------------------
// Kernel 1: pooled[b,:] = (sum_n w_n * x[b,n,:]) @ W
// ---------------------------------------------------------------------------
#define PK_NT 128
__global__ __launch_bounds__(PK_NT)
void pooled_kernel(const float* __restrict__ x,
                   const float* __restrict__ A,
                   const float* __restrict__ W) {
    __shared__ float sx[PK_NT * 3 * DIM];
    __shared__ float sW[DIM * DIM];
    __shared__ float sw[3];
    int tid = threadIdx.x;
    if (tid < DIM * DIM) sW[tid] = W[tid];
    if (tid < 3) {
        const float offsum[3] = {1.f, 1.f, 2.f};
        sw[tid] = 0.125f * (offsum[tid] + A[tid] + A[3 + tid]);
    }
    // vectorized staging: PK_NT*30 floats = PK_NT*7.5 float4 (divisible: 960)
    const float4* xs = (const float4*)(x + blockIdx.x * PK_NT * 3 * DIM);
    float4* sd = (float4*)sx;
    #pragma unroll
    for (int i = tid; i < PK_NT * 3 * DIM / 4; i += PK_NT)
        sd[i] = xs[i];
    __syncthreads();

    const float* xb = &sx[tid * 3 * DIM];
    float w0 = sw[0], w1 = sw[1], w2 = sw[2];
    float y[DIM];
    #pragma unroll
    for (int f = 0; f < DIM; f++)
        y[f] = fmaf(w2, xb[2 * DIM + f], fmaf(w1, xb[DIM + f], w0 * xb[f]));
    int b = blockIdx.x * PK_NT + tid;
    #pragma unroll
    for (int o = 0; o < DIM; o++) {
        float acc = 0.f;
        #pragma unroll
        for (int f = 0; f < DIM; f++)
            acc = fmaf(y[f], sW[f * DIM + o], acc);
        g_pooled[b * DIM + o] = acc;
    }
}

// ---------------------------------------------------------------------------
// Kernel 2: out = softmax(P P^T) P, flash-style.
// NT=128 = 4 warps; each warp (PARTS=32 lanes) owns QPT=2 queries.
// BQ=8 queries/CTA, grid=1024 -> 131072 threads (2x R5 concurrency).
// SMEM keys in 5 feature-planes of f32x2, double-buffered cp.async.
// ---------------------------------------------------------------------------
#define TILE 256
#define NTILES (BATCH / TILE)
#define NT 128
#define PARTS 32
#define QPT 2
#define BQ 8

__global__ __launch_bounds__(NT)
void attn_kernel(float* __restrict__ out) {
    // 2 buffers x 5 planes x TILE x 8B = 20480 B
    __shared__ __align__(16) float sk[2][5 * TILE * 2];

    int tid = threadIdx.x;
    int grp = tid >> 5;         // warp 0..3
    int p   = tid & 31;         // lane = key-part
    int myq = blockIdx.x * BQ + grp * QPT;

    u32 sbase = smem_u32(&sk[0][0]);
    const u32 BUFB = 5 * TILE * 8;   // bytes per buffer

    // queries (pre-scaled by log2e)
    u64 q[QPT][5];
    #pragma unroll
    for (int u = 0; u < QPT; u++)
        #pragma unroll
        for (int h = 0; h < 5; h++) {
            float2 v = *(const float2*)&g_pooled[(myq + u) * DIM + 2 * h];
            q[u][h] = pack2(v.x * LOG2E, v.y * LOG2E);
        }

    u64 acc[QPT][5];
    float esum[QPT];
    #pragma unroll
    for (int u = 0; u < QPT; u++) {
        esum[u] = 0.f;
        #pragma unroll
        for (int h = 0; h < 5; h++) acc[u][h] = pack2(0.f, 0.f);
    }

    // tile fill: row r -> plane c at (c*TILE + r)*8 within buffer
    auto fill_tile = [&](int t, int buf) {
        const float* src = g_pooled + t * TILE * DIM;
        u32 dbase = sbase + buf * BUFB;
        #pragma unroll
        for (int r = tid; r < TILE; r += NT) {
            const float* s = src + r * DIM;
            u32 d = dbase + r * 8u;
            #pragma unroll
            for (int c = 0; c < 5; c++)
                asm volatile("cp.async.ca.shared.global [%0], [%1], 8;"
                             :: "r"(d + (u32)(c * TILE * 8)), "l"(s + 2 * c));
        }
        asm volatile("cp.async.commit_group;");
    };

    fill_tile(0, 0);

    for (int t = 0; t < NTILES; t++) {
        asm volatile("cp.async.wait_group 0;");
        __syncthreads();
        if (t + 1 < NTILES) fill_tile(t + 1, (t + 1) & 1);

        u32 kbase = sbase + (t & 1) * BUFB;
        #pragma unroll
        for (int j = p; j < TILE; j += 2 * PARTS) {   // 4 iterations
            u32 oa = kbase + j * 8u;
            u32 ob = oa + PARTS * 8u;
            u64 a0 = lds64(oa);
            u64 a1 = lds64(oa + 1 * TILE * 8);
            u64 a2 = lds64(oa + 2 * TILE * 8);
            u64 a3 = lds64(oa + 3 * TILE * 8);
            u64 a4 = lds64(oa + 4 * TILE * 8);
            u64 b0 = lds64(ob);
            u64 b1 = lds64(ob + 1 * TILE * 8);
            u64 b2 = lds64(ob + 2 * TILE * 8);
            u64 b3 = lds64(ob + 3 * TILE * 8);
            u64 b4 = lds64(ob + 4 * TILE * 8);
            #pragma unroll
            for (int u = 0; u < QPT; u++) {
                u64 sA = mul2(q[u][0], a0);
                u64 sB = mul2(q[u][0], b0);
                sA = fma2(q[u][1], a1, sA);
                sB = fma2(q[u][1], b1, sB);
                sA = fma2(q[u][2], a2, sA);
                sB = fma2(q[u][2], b2, sB);
                sA = fma2(q[u][3], a3, sA);
                sB = fma2(q[u][3], b3, sB);
                sA = fma2(q[u][4], a4, sA);
                sB = fma2(q[u][4], b4, sB);
                float2 fA = unpack2(sA);
                float2 fB = unpack2(sB);
                float eA = ex2f(fA.x + fA.y);
                float eB = ex2f(fB.x + fB.y);
                esum[u] += eA + eB;
                u64 ea = pack2(eA, eA);
                u64 eb = pack2(eB, eB);
                acc[u][0] = fma2(ea, a0, acc[u][0]);
                acc[u][1] = fma2(ea, a1, acc[u][1]);
                acc[u][2] = fma2(ea, a2, acc[u][2]);
                acc[u][3] = fma2(ea, a3, acc[u][3]);
                acc[u][4] = fma2(ea, a4, acc[u][4]);
                acc[u][0] = fma2(eb, b0, acc[u][0]);
                acc[u][1] = fma2(eb, b1, acc[u][1]);
                acc[u][2] = fma2(eb, b2, acc[u][2]);
                acc[u][3] = fma2(eb, b3, acc[u][3]);
                acc[u][4] = fma2(eb, b4, acc[u][4]);
            }
        }
    }

    // full-warp reduction (32 key-part lanes per query pair)
    #pragma unroll
    for (int off = 16; off >= 1; off >>= 1) {
        #pragma unroll
        for (int u = 0; u < QPT; u++) {
            esum[u] += __shfl_down_sync(0xffffffffu, esum[u], off);
            #pragma unroll
            for (int h = 0; h < 5; h++) {
                u64 other = __shfl_down_sync(0xffffffffu, acc[u][h], off);
                acc[u][h] = add2(acc[u][h], other);
            }
        }
    }

    if (p == 0) {
        #pragma unroll
        for (int u = 0; u < QPT; u++) {
            float inv = 1.0f / esum[u];
            float* orow = &out[(myq + u) * DIM];
            #pragma unroll
            for (int h = 0; h < 5; h++) {
                float2 v = unpack2(acc[u][h]);
                float2 o; o.x = v.x * inv; o.y = v.y * inv;
                *(float2*)(orow + 2 * h) = o;
            }
        }
    }
}

// ---------------------------------------------------------------------------
extern "C" void kernel_launch(void* const* d_in, const int* in_sizes, int n_in,
                              void* d_out, int out_size) {
    const float* x = (const float*)d_in[0];   // [8192, 3, 10]
    const float* A = (const float*)d_in[1];   // [3, 3]
    const float* W = (const float*)d_in[2];   // [10, 10]
    float* out = (float*)d_out;               // [8192, 10]

    pooled_kernel<<<BATCH / PK_NT, PK_NT>>>(x, A, W);
    attn_kernel<<<BATCH / BQ, NT>>>(out);
}

// round 8
// speedup vs baseline: 2.4845x; 1.0500x over previous
#include <cuda_runtime.h>
#include <cuda_bf16.h>
#include <cstdint>

#define BATCH 8192
#define DIM 10
#define LOG2E 1.4426950408889634f

__device__ float g_pooled[BATCH * DIM];

typedef unsigned long long u64;
typedef unsigned int u32;

__device__ __forceinline__ u64 pack2(float lo, float hi) {
    u64 r; asm("mov.b64 %0, {%1, %2};" : "=l"(r) : "f"(lo), "f"(hi)); return r;
}
__device__ __forceinline__ float2 unpack2(u64 v) {
    float2 f; asm("mov.b64 {%0, %1}, %2;" : "=f"(f.x), "=f"(f.y) : "l"(v)); return f;
}
__device__ __forceinline__ u64 fma2(u64 a, u64 b, u64 c) {
    u64 d; asm("fma.rn.f32x2 %0, %1, %2, %3;" : "=l"(d) : "l"(a), "l"(b), "l"(c)); return d;
}
__device__ __forceinline__ u64 mul2(u64 a, u64 b) {
    u64 d; asm("mul.rn.f32x2 %0, %1, %2;" : "=l"(d) : "l"(a), "l"(b)); return d;
}
__device__ __forceinline__ float ex2f(float x) {
    float y; asm("ex2.approx.f32 %0, %1;" : "=f"(y) : "f"(x)); return y;
}
__device__ __forceinline__ u32 smem_u32(const void* p) {
    u32 a;
    asm("{ .reg .u64 t; cvta.to.shared.u64 t, %1; cvt.u32.u64 %0, t; }"
        : "=r"(a) : "l"(p));
    return a;
}
__device__ __forceinline__ u64 lds64(u32 addr) {
    u64 v; asm volatile("ld.shared.b64 %0, [%1];" : "=l"(v) : "r"(addr)); return v;
}

// ---------------------------------------------------------------------------
// Kernel 1: pooled[b,:] = (sum_n w_n * x[b,n,:]) @ W
// ---------------------------------------------------------------------------
#define PK_NT 128
__global__ __launch_bounds__(PK_NT)
void pooled_kernel(const float* __restrict__ x,
                   const float* __restrict__ A,
                   const float* __restrict__ W) {
    __shared__ float sx[PK_NT * 3 * DIM];
    __shared__ float sW[DIM * DIM];
    __shared__ float sw[3];
    int tid = threadIdx.x;
    if (tid < DIM * DIM) sW[tid] = W[tid];
    if (tid < 3) {
        const float offsum[3] = {1.f, 1.f, 2.f};
        sw[tid] = 0.125f * (offsum[tid] + A[tid] + A[3 + tid]);
    }
    const float4* xs = (const float4*)(x + blockIdx.x * PK_NT * 3 * DIM);
    float4* sd = (float4*)sx;
    #pragma unroll
    for (int i = tid; i < PK_NT * 3 * DIM / 4; i += PK_NT)
        sd[i] = xs[i];
    __syncthreads();

    const float* xb = &sx[tid * 3 * DIM];
    float w0 = sw[0], w1 = sw[1], w2 = sw[2];
    float y[DIM];
    #pragma unroll
    for (int f = 0; f < DIM; f++)
        y[f] = fmaf(w2, xb[2 * DIM + f], fmaf(w1, xb[DIM + f], w0 * xb[f]));
    int b = blockIdx.x * PK_NT + tid;
    #pragma unroll
    for (int o = 0; o < DIM; o++) {
        float acc = 0.f;
        #pragma unroll
        for (int f = 0; f < DIM; f++)
            acc = fmaf(y[f], sW[f * DIM + o], acc);
        g_pooled[b * DIM + o] = acc;
    }
}

// ---------------------------------------------------------------------------
// Kernel 2: out = softmax(P P^T) P, flash-style.
// PARTS=64 (two warps) per query-quad, QPT=4: key LDS amortized 4x.
// NT=128, BQ=8, grid=1024 -> 131072 threads (same concurrency as R6).
// Keys in 5 f32x2 feature-planes, double-buffered cp.async.
// ---------------------------------------------------------------------------
#define TILE 512
#define NTILES (BATCH / TILE)
#define NT 128
#define PARTS 64
#define QPT 4
#define BQ 8     // (NT/PARTS)*QPT

__global__ __launch_bounds__(NT)
void attn_kernel(float* __restrict__ out) {
    // 2 buffers x 5 planes x TILE x 8B = 40960 B (also reused for reduction)
    __shared__ __align__(16) float sk[2][5 * TILE * 2];

    int tid  = threadIdx.x;
    int grp  = tid >> 6;        // 0..1 : query-quad group (2 warps)
    int p    = tid & 63;        // key-part within group
    int wid  = tid >> 5;        // warp 0..3
    int lane = tid & 31;
    int myq  = blockIdx.x * BQ + grp * QPT;

    u32 sbase = smem_u32(&sk[0][0]);
    const u32 BUFB = 5 * TILE * 8;

    // queries (pre-scaled by log2e)
    u64 q[QPT][5];
    #pragma unroll
    for (int u = 0; u < QPT; u++)
        #pragma unroll
        for (int h = 0; h < 5; h++) {
            float2 v = *(const float2*)&g_pooled[(myq + u) * DIM + 2 * h];
            q[u][h] = pack2(v.x * LOG2E, v.y * LOG2E);
        }

    u64 acc[QPT][5];
    float esum[QPT];
    #pragma unroll
    for (int u = 0; u < QPT; u++) {
        esum[u] = 0.f;
        #pragma unroll
        for (int h = 0; h < 5; h++) acc[u][h] = pack2(0.f, 0.f);
    }

    auto fill_tile = [&](int t, int buf) {
        const float* src = g_pooled + t * TILE * DIM;
        u32 dbase = sbase + buf * BUFB;
        #pragma unroll
        for (int r = tid; r < TILE; r += NT) {
            const float* s = src + r * DIM;
            u32 d = dbase + r * 8u;
            #pragma unroll
            for (int c = 0; c < 5; c++)
                asm volatile("cp.async.ca.shared.global [%0], [%1], 8;"
                             :: "r"(d + (u32)(c * TILE * 8)), "l"(s + 2 * c));
        }
        asm volatile("cp.async.commit_group;");
    };

    fill_tile(0, 0);

    for (int t = 0; t < NTILES; t++) {
        asm volatile("cp.async.wait_group 0;");
        __syncthreads();
        if (t + 1 < NTILES) fill_tile(t + 1, (t + 1) & 1);

        u32 kbase = sbase + (t & 1) * BUFB;
        #pragma unroll
        for (int j = p; j < TILE; j += PARTS) {   // 8 iterations
            u32 oa = kbase + j * 8u;
            u64 k0 = lds64(oa);
            u64 k1 = lds64(oa + 1 * TILE * 8);
            u64 k2 = lds64(oa + 2 * TILE * 8);
            u64 k3 = lds64(oa + 3 * TILE * 8);
            u64 k4 = lds64(oa + 4 * TILE * 8);
            // 4 independent dot chains
            u64 s0 = mul2(q[0][0], k0);
            u64 s1 = mul2(q[1][0], k0);
            u64 s2 = mul2(q[2][0], k0);
            u64 s3 = mul2(q[3][0], k0);
            s0 = fma2(q[0][1], k1, s0);
            s1 = fma2(q[1][1], k1, s1);
            s2 = fma2(q[2][1], k1, s2);
            s3 = fma2(q[3][1], k1, s3);
            s0 = fma2(q[0][2], k2, s0);
            s1 = fma2(q[1][2], k2, s1);
            s2 = fma2(q[2][2], k2, s2);
            s3 = fma2(q[3][2], k2, s3);
            s0 = fma2(q[0][3], k3, s0);
            s1 = fma2(q[1][3], k3, s1);
            s2 = fma2(q[2][3], k3, s2);
            s3 = fma2(q[3][3], k3, s3);
            s0 = fma2(q[0][4], k4, s0);
            s1 = fma2(q[1][4], k4, s1);
            s2 = fma2(q[2][4], k4, s2);
            s3 = fma2(q[3][4], k4, s3);
            float2 f0 = unpack2(s0);
            float2 f1 = unpack2(s1);
            float2 f2 = unpack2(s2);
            float2 f3 = unpack2(s3);
            float e0 = ex2f(f0.x + f0.y);
            float e1 = ex2f(f1.x + f1.y);
            float e2 = ex2f(f2.x + f2.y);
            float e3 = ex2f(f3.x + f3.y);
            esum[0] += e0; esum[1] += e1; esum[2] += e2; esum[3] += e3;
            u64 ee0 = pack2(e0, e0);
            u64 ee1 = pack2(e1, e1);
            u64 ee2 = pack2(e2, e2);
            u64 ee3 = pack2(e3, e3);
            acc[0][0] = fma2(ee0, k0, acc[0][0]);
            acc[1][0] = fma2(ee1, k0, acc[1][0]);
            acc[2][0] = fma2(ee2, k0, acc[2][0]);
            acc[3][0] = fma2(ee3, k0, acc[3][0]);
            acc[0][1] = fma2(ee0, k1, acc[0][1]);
            acc[1][1] = fma2(ee1, k1, acc[1][1]);
            acc[2][1] = fma2(ee2, k1, acc[2][1]);
            acc[3][1] = fma2(ee3, k1, acc[3][1]);
            acc[0][2] = fma2(ee0, k2, acc[0][2]);
            acc[1][2] = fma2(ee1, k2, acc[1][2]);
            acc[2][2] = fma2(ee2, k2, acc[2][2]);
            acc[3][2] = fma2(ee3, k2, acc[3][2]);
            acc[0][3] = fma2(ee0, k3, acc[0][3]);
            acc[1][3] = fma2(ee1, k3, acc[1][3]);
            acc[2][3] = fma2(ee2, k3, acc[2][3]);
            acc[3][3] = fma2(ee3, k3, acc[3][3]);
            acc[0][4] = fma2(ee0, k4, acc[0][4]);
            acc[1][4] = fma2(ee1, k4, acc[1][4]);
            acc[2][4] = fma2(ee2, k4, acc[2][4]);
            acc[3][4] = fma2(ee3, k4, acc[3][4]);
        }
    }

    // intra-warp reduction (each warp holds partials over its 32 key-parts)
    #pragma unroll
    for (int off = 16; off >= 1; off >>= 1) {
        #pragma unroll
        for (int u = 0; u < QPT; u++) {
            esum[u] += __shfl_down_sync(0xffffffffu, esum[u], off);
            #pragma unroll
            for (int h = 0; h < 5; h++) {
                u64 other = __shfl_down_sync(0xffffffffu, acc[u][h], off);
                float2 a = unpack2(acc[u][h]);
                float2 b = unpack2(other);
                acc[u][h] = pack2(a.x + b.x, a.y + b.y);
            }
        }
    }

    // cross-warp combine via SMEM (overlay on sk; all reads of sk are done)
    __syncthreads();
    float* sred = &sk[0][0];    // [warp][u][12]: 10 acc + esum
    if (lane == 0) {
        #pragma unroll
        for (int u = 0; u < QPT; u++) {
            float* dst = sred + (wid * QPT + u) * 12;
            #pragma unroll
            for (int h = 0; h < 5; h++) {
                float2 v = unpack2(acc[u][h]);
                dst[2 * h] = v.x; dst[2 * h + 1] = v.y;
            }
            dst[10] = esum[u];
        }
    }
    __syncthreads();

    // 2 groups x 4 queries x 10 feats = 80 output elements
    if (tid < BQ * DIM) {
        int g = tid / (QPT * DIM);
        int u = (tid / DIM) % QPT;
        int f = tid % DIM;
        const float* w0p = sred + ((2 * g) * QPT + u) * 12;
        const float* w1p = sred + ((2 * g + 1) * QPT + u) * 12;
        float v  = w0p[f] + w1p[f];
        float es = w0p[10] + w1p[10];
        out[(blockIdx.x * BQ + g * QPT + u) * DIM + f] = v / es;
    }
}

// ---------------------------------------------------------------------------
extern "C" void kernel_launch(void* const* d_in, const int* in_sizes, int n_in,
                              void* d_out, int out_size) {
    const float* x = (const float*)d_in[0];   // [8192, 3, 10]
    const float* A = (const float*)d_in[1];   // [3, 3]
    const float* W = (const float*)d_in[2];   // [10, 10]
    float* out = (float*)d_out;               // [8192, 10]

    pooled_kernel<<<BATCH / PK_NT, PK_NT>>>(x, A, W);
    attn_kernel<<<BATCH / BQ, NT>>>(out);
}